// round 13
// baseline (speedup 1.0000x reference)
#include <cuda_runtime.h>
#include <cuda_fp16.h>
#include <cstdint>

// QKVAttentionLegacy, pure fp16 mma.sync, fp32 accum.
// R13 = split-S: CTA 128 thr / 64 queries; 4 warps = 2 query-groups x 2
// key-slices of 32. Each K/V fragment is loaded by only ONE warp ->
// per-CTA LDSM halves vs R10 (L1 was top pipe at 68%) while grid stays
// 1024 (2 waves, no R11 tail) and per-warp phases stay short.
// Triple-buffer ring, one barrier per tile. Cross-warp O/l combine at end.
// bs=2, heads=16 -> 32 bh, ch=64, T=2048, S=2560; 40 key tiles of 64.

#define NTHREADS 128
#define NS_TILES 40
#define TILE_BYTES 16384          // K(8KB) | V(8KB) fp16 swizzled images

#define SM_Q    0                  // Q tile: 64t x 64c fp16 = 8KB
#define SM_BUF0 8192               // 3 x 16KB ring
#define SM_TOTAL (8192 + 3 * TILE_BYTES)   // 57344 B; x4 CTAs/SM fits

// scratch: [32 bh][40 tiles][16KB tile image]
__device__ __align__(16) char g_scratch[32u * NS_TILES * TILE_BYTES];

static __device__ __forceinline__ uint32_t swz(uint32_t r, uint32_t c) {
    // byte offset of element (row r, col c) in a [*][64] fp16 tile
    return (r << 7) + ((((c >> 3) ^ (r & 7)) & 7) << 4) + ((c & 7) << 1);
}
static __device__ __forceinline__ uint32_t smem_u32(const void* p) {
    uint32_t a;
    asm("{ .reg .u64 t; cvta.to.shared.u64 t, %1; cvt.u32.u64 %0, t; }" : "=r"(a) : "l"(p));
    return a;
}
static __device__ __forceinline__ float ex2(float x) {
    float y; asm("ex2.approx.f32 %0, %1;" : "=f"(y) : "f"(x));
    return y;
}

#define LDSM_X4(R0,R1,R2,R3,A) \
    asm volatile("ldmatrix.sync.aligned.m8n8.x4.shared.b16 {%0,%1,%2,%3}, [%4];" \
        : "=r"(R0),"=r"(R1),"=r"(R2),"=r"(R3) : "r"(A))
#define LDSM_X4T(R0,R1,R2,R3,A) \
    asm volatile("ldmatrix.sync.aligned.m8n8.x4.trans.shared.b16 {%0,%1,%2,%3}, [%4];" \
        : "=r"(R0),"=r"(R1),"=r"(R2),"=r"(R3) : "r"(A))
#define MMA16816(D, A0,A1,A2,A3, B0,B1) \
    asm volatile("mma.sync.aligned.m16n8k16.row.col.f32.f16.f16.f32 " \
        "{%0,%1,%2,%3}, {%4,%5,%6,%7}, {%8,%9}, {%0,%1,%2,%3};" \
        : "+f"((D)[0]),"+f"((D)[1]),"+f"((D)[2]),"+f"((D)[3]) \
        : "r"(A0),"r"(A1),"r"(A2),"r"(A3),"r"(B0),"r"(B1))

static __device__ __forceinline__ void cpa16(uint32_t dst, const void* src) {
    asm volatile("cp.async.cg.shared.global [%0], [%1], 16;" :: "r"(dst), "l"(src));
}
#define CP_COMMIT() asm volatile("cp.async.commit_group;" ::: "memory")
#define CP_WAIT(n)  asm volatile("cp.async.wait_group %0;" :: "n"(n) : "memory")

// ---- prologue: one 64x64 fp32 tile -> fp16 swizzled image ----
static __device__ __forceinline__ void conv_tile(
    const float* __restrict__ src, size_t stride, char* dst, int tid)
{
    const int c  = tid >> 2;
    const int s0 = (tid & 3) << 4;
    const float* p = src + (size_t)c * stride + s0;
    float4 f[4];
    f[0] = *(const float4*)(p);
    f[1] = *(const float4*)(p + 4);
    f[2] = *(const float4*)(p + 8);
    f[3] = *(const float4*)(p + 12);
    const float* v = (const float*)f;
    uint32_t h[8];
    #pragma unroll
    for (int i = 0; i < 8; ++i) {
        __half2 hh = __floats2half2_rn(v[2 * i], v[2 * i + 1]);
        h[i] = *(uint32_t*)&hh;
    }
    *(uint4*)(dst + swz(c, s0))     = make_uint4(h[0], h[1], h[2], h[3]);
    *(uint4*)(dst + swz(c, s0 + 8)) = make_uint4(h[4], h[5], h[6], h[7]);
}

__global__ __launch_bounds__(256) void conv_kv_kernel(
    const float* __restrict__ qkv, const float* __restrict__ ekv)
{
    const int st = blockIdx.x;   // 0..39
    const int bh = blockIdx.y;   // 0..31
    const int b = bh >> 4, h = bh & 15;
    const float* qbase  = qkv + ((size_t)b * 3072 + (size_t)h * 192) * 2048;
    const float* kbase  = qbase + (size_t)64  * 2048;
    const float* vbase  = qbase + (size_t)128 * 2048;
    const float* ekbase = ekv + ((size_t)b * 2048 + (size_t)h * 128) * 512;
    const float* evbase = ekbase + (size_t)64 * 512;

    const float* ksrc; const float* vsrc; size_t stride;
    if (st < 8) { ksrc = ekbase + st * 64; vsrc = evbase + st * 64; stride = 512; }
    else        { ksrc = kbase + (st - 8) * 64; vsrc = vbase + (st - 8) * 64; stride = 2048; }

    char* dst = g_scratch + ((size_t)bh * NS_TILES + st) * TILE_BYTES;
    conv_tile(ksrc, stride, dst,        threadIdx.x);
    conv_tile(vsrc, stride, dst + 8192, threadIdx.x);
}

__global__ __launch_bounds__(NTHREADS, 4) void qkv_attn_mma(
    const float* __restrict__ qkv,
    float* __restrict__ out)
{
    extern __shared__ char smb[];
    const uint32_t sb = smem_u32(smb);
    const int tid  = threadIdx.x;
    const int wid  = tid >> 5;          // 0..3
    const int lane = tid & 31;
    const int qg   = wid >> 1;          // query group: rows [qg*32, qg*32+32)
    const int ksl  = wid & 1;           // key slice: cols [ksl*32, ksl*32+32)
    const int m0   = qg * 32;
    const int scol0 = ksl * 32;

    const int t_tile = blockIdx.x;      // 0..31 (64-query tiles)
    const int bh     = blockIdx.y;      // 0..31
    const int b = bh >> 4;
    const int h = bh & 15;
    const int t0 = t_tile * 64;

    const float* qbase = qkv + ((size_t)b * 3072 + (size_t)h * 192) * 2048;
    const char*  kv0   = g_scratch + (size_t)bh * NS_TILES * TILE_BYTES;

    // ---- start tile 0 load (16KB / 128 thr = 8 x 16B each) ----
    {
        const char* src = kv0 + tid * 16;
        uint32_t d = sb + SM_BUF0 + tid * 16;
        #pragma unroll
        for (int i = 0; i < 8; ++i) cpa16(d + i * 2048, src + i * 2048);
        CP_COMMIT();
    }

    // ---- stage Q [64t x 64c] fp16 (transpose + scale*log2e) ----
    #pragma unroll 1
    for (int ci = 0; ci < 16; ++ci) {
        int c = wid + 4 * ci;
        const float* qrow = qbase + (size_t)c * 2048 + t0;
        #pragma unroll
        for (int j = 0; j < 2; ++j) {
            int t = lane + 32 * j;
            float x = qrow[t] * (0.125f * 1.44269504f);
            *(__half*)(smb + SM_Q + swz(t, c)) = __float2half_rn(x);
        }
    }
    __syncthreads();

    // ---- Q A-fragments for this warp's 32 rows, kept for all 40 tiles ----
    uint32_t qh[2][4][4];
    {
        int qcg = (lane >> 4) << 3;
        #pragma unroll
        for (int rb = 0; rb < 2; ++rb) {
            int qr = m0 + rb * 16 + (lane & 15);
            #pragma unroll
            for (int ks = 0; ks < 4; ++ks)
                LDSM_X4(qh[rb][ks][0], qh[rb][ks][1], qh[rb][ks][2], qh[rb][ks][3],
                        sb + SM_Q + swz(qr, ks * 16 + qcg));
        }
    }

    float o[2][8][4];
    #pragma unroll
    for (int rb = 0; rb < 2; ++rb)
        #pragma unroll
        for (int j = 0; j < 8; ++j)
            #pragma unroll
            for (int r = 0; r < 4; ++r) o[rb][j][r] = 0.0f;
    float lsum[2][2] = {{0.f, 0.f}, {0.f, 0.f}};

    const int krow = lane & 15;               // + ks*16
    const int kcol = (lane >> 4) << 3;        // + scolh
    const int vrow = (lane & 7) + ((lane >> 4) << 3);   // + ng*16
    const int vcol = ((lane >> 3) & 1) << 3;            // + scolh

    // ring slot bases: cur = st%3, nxt = (st+1)%3
    uint32_t cur_b = sb + SM_BUF0;
    uint32_t nxt_b = sb + SM_BUF0 + TILE_BYTES;

    #pragma unroll 1
    for (int st = 0; st < NS_TILES; ++st) {
        if (st + 1 < NS_TILES) {
            const char* src = kv0 + (size_t)(st + 1) * TILE_BYTES + tid * 16;
            uint32_t d = nxt_b + tid * 16;
            #pragma unroll
            for (int i = 0; i < 8; ++i) cpa16(d + i * 2048, src + i * 2048);
            CP_COMMIT();
            CP_WAIT(1);
        } else {
            CP_WAIT(0);
        }
        __syncthreads();   // only barrier per tile (triple buffer)

        const uint32_t kh_b = cur_b;             // K fp16 image [c][s]
        const uint32_t vh_b = cur_b + 8192;      // V fp16 image [c][s]
        cur_b = nxt_b;
        nxt_b = nxt_b + TILE_BYTES;
        if (nxt_b == sb + SM_BUF0 + 3 * TILE_BYTES) nxt_b = sb + SM_BUF0;

        // this warp's 32-key slice, in two 16-key halves
        #pragma unroll
        for (int hf = 0; hf < 2; ++hf) {
            const int scolh = scol0 + hf * 16;

            // ---- GEMM1: d[rb][2 n8][4] = Q x K-slice ----
            float d[2][2][4];
            #pragma unroll
            for (int rb = 0; rb < 2; ++rb)
                #pragma unroll
                for (int j = 0; j < 2; ++j)
                    #pragma unroll
                    for (int r = 0; r < 4; ++r) d[rb][j][r] = 0.0f;

            #pragma unroll
            for (int ks = 0; ks < 4; ++ks) {
                uint32_t b0, b1, b2, b3;
                LDSM_X4T(b0, b1, b2, b3, kh_b + swz(ks * 16 + krow, scolh + kcol));
                #pragma unroll
                for (int rb = 0; rb < 2; ++rb) {
                    MMA16816(d[rb][0], qh[rb][ks][0], qh[rb][ks][1], qh[rb][ks][2], qh[rb][ks][3], b0, b1);
                    MMA16816(d[rb][1], qh[rb][ks][0], qh[rb][ks][1], qh[rb][ks][2], qh[rb][ks][3], b2, b3);
                }
            }

            // ---- softmax p = 2^score; pack P A-fragment (k-step = this half) ----
            uint32_t pa[2][4];
            #pragma unroll
            for (int rb = 0; rb < 2; ++rb) {
                #pragma unroll
                for (int j = 0; j < 2; ++j) {
                    float p0 = ex2(d[rb][j][0]);
                    float p1 = ex2(d[rb][j][1]);
                    float p2 = ex2(d[rb][j][2]);
                    float p3 = ex2(d[rb][j][3]);
                    lsum[rb][0] += p0 + p1;
                    lsum[rb][1] += p2 + p3;
                    __half2 h01 = __floats2half2_rn(p0, p1);
                    __half2 h23 = __floats2half2_rn(p2, p3);
                    pa[rb][2 * j]     = *(uint32_t*)&h01;
                    pa[rb][2 * j + 1] = *(uint32_t*)&h23;
                }
            }

            // ---- GEMM2: O += P x V-slice (k = 16 keys of this half) ----
            #pragma unroll
            for (int ng = 0; ng < 4; ++ng) {
                uint32_t b0, b1, b2, b3;
                LDSM_X4(b0, b1, b2, b3, vh_b + swz(ng * 16 + vrow, scolh + vcol));
                #pragma unroll
                for (int rb = 0; rb < 2; ++rb) {
                    MMA16816(o[rb][2 * ng],     pa[rb][0], pa[rb][1], pa[rb][2], pa[rb][3], b0, b1);
                    MMA16816(o[rb][2 * ng + 1], pa[rb][0], pa[rb][1], pa[rb][2], pa[rb][3], b2, b3);
                }
            }
        }
    }

    // ---- epilogue: combine the two key-slice warps of each query group ----
    float l0r[2], l1r[2];
    #pragma unroll
    for (int rb = 0; rb < 2; ++rb) {
        float a = lsum[rb][0], bsv = lsum[rb][1];
        a   += __shfl_xor_sync(0xffffffffu, a, 1);
        a   += __shfl_xor_sync(0xffffffffu, a, 2);
        bsv += __shfl_xor_sync(0xffffffffu, bsv, 1);
        bsv += __shfl_xor_sync(0xffffffffu, bsv, 2);
        l0r[rb] = a; l1r[rb] = bsv;
    }
    __syncthreads();   // all warps done with ring smem

    const int OS = 72;  // padded row stride (floats) to soften bank conflicts
    float* Osm = (float*)(smb + SM_BUF0) + qg * 3072;   // 32*72 = 2304 fl + l
    float* Lsm = Osm + 2304;

    if (ksl == 1) {
        #pragma unroll
        for (int rb = 0; rb < 2; ++rb) {
            int q = rb * 16 + (lane >> 2);
            #pragma unroll
            for (int j = 0; j < 8; ++j) {
                int c = j * 8 + (lane & 3) * 2;
                Osm[q * OS + c]           = o[rb][j][0];
                Osm[q * OS + c + 1]       = o[rb][j][1];
                Osm[(q + 8) * OS + c]     = o[rb][j][2];
                Osm[(q + 8) * OS + c + 1] = o[rb][j][3];
            }
            if ((lane & 3) == 0) { Lsm[q] = l0r[rb]; Lsm[q + 8] = l1r[rb]; }
        }
    }
    __syncthreads();
    if (ksl == 0) {
        #pragma unroll
        for (int rb = 0; rb < 2; ++rb) {
            int q = rb * 16 + (lane >> 2);
            float rl0 = 1.0f / (l0r[rb] + Lsm[q]);
            float rl1 = 1.0f / (l1r[rb] + Lsm[q + 8]);
            int tg = t0 + m0 + q;
            #pragma unroll
            for (int j = 0; j < 8; ++j) {
                int c = j * 8 + (lane & 3) * 2;
                float* p = out + ((size_t)(b * 1024 + h * 64 + c)) * 2048 + tg;
                p[0]        = (o[rb][j][0] + Osm[q * OS + c])           * rl0;
                p[2048]     = (o[rb][j][1] + Osm[q * OS + c + 1])       * rl0;
                p[8]        = (o[rb][j][2] + Osm[(q + 8) * OS + c])     * rl1;
                p[2048 + 8] = (o[rb][j][3] + Osm[(q + 8) * OS + c + 1]) * rl1;
            }
        }
    }
}

extern "C" void kernel_launch(void* const* d_in, const int* in_sizes, int n_in,
                              void* d_out, int out_size)
{
    const float* qkv;
    const float* ekv;
    if (in_sizes[0] == 2 * 3072 * 2048) {
        qkv = (const float*)d_in[0];
        ekv = (const float*)d_in[1];
    } else {
        qkv = (const float*)d_in[1];
        ekv = (const float*)d_in[0];
    }
    float* out = (float*)d_out;

    // prologue: pre-convert K/V to fp16 swizzled tile images
    dim3 cgrid(NS_TILES, 32);
    conv_kv_kernel<<<cgrid, 256>>>(qkv, ekv);

    cudaFuncSetAttribute(qkv_attn_mma,
                         cudaFuncAttributeMaxDynamicSharedMemorySize, SM_TOTAL);
    dim3 grid(32, 32);   // (t-tiles of 64, batch-heads)
    qkv_attn_mma<<<grid, NTHREADS, SM_TOTAL>>>(qkv, out);
}

// round 14
// speedup vs baseline: 1.1447x; 1.1447x over previous
#include <cuda_runtime.h>
#include <cuda_fp16.h>
#include <cstdint>

// QKVAttentionLegacy, pure fp16 mma.sync, fp32 accum.
// R14 = R12 (4 warps x 16 q-rows, 128 thr, 4 CTAs/SM, triple-buffer ring,
// one barrier/tile) + LDSM-NATIVE LINEAR TILE LAYOUT: the prologue stores
// each 64-key tile as 32 fragment blobs of 512B in exactly the order
// (non-trans) ldmatrix consumes. Every ldmatrix address = base + immediate
// (+ lane*16 precomputed once), eliminating the per-tile swizzle ALU that
// the 128-reg cap prevented ptxas from hoisting (R12: alu 16%).
// Register contents are bit-identical to R12's swizzled LDSM_X4T/X4 loads.
// bs=2, heads=16 -> 32 bh, ch=64, T=2048, S=2560; 40 key tiles of 64.

#define NTHREADS 128
#define NS_TILES 40
#define TILE_BYTES 16384          // Kblob(8KB) | Vblob(8KB)

#define SM_Q    0                  // Q tile: 64t x 64c fp16 = 8KB (swizzled)
#define SM_BUF0 8192               // 3 x 16KB ring
#define SM_TOTAL (8192 + 3 * TILE_BYTES)   // 57344 B; x4 CTAs/SM fits

// scratch: [32 bh][40 tiles][16KB blob]
__device__ __align__(16) char g_scratch[32u * NS_TILES * TILE_BYTES];

static __device__ __forceinline__ uint32_t swz(uint32_t r, uint32_t c) {
    // byte offset of element (row r, col c) in a [*][64] fp16 tile (Q only)
    return (r << 7) + ((((c >> 3) ^ (r & 7)) & 7) << 4) + ((c & 7) << 1);
}
static __device__ __forceinline__ uint32_t smem_u32(const void* p) {
    uint32_t a;
    asm("{ .reg .u64 t; cvta.to.shared.u64 t, %1; cvt.u32.u64 %0, t; }" : "=r"(a) : "l"(p));
    return a;
}
static __device__ __forceinline__ float ex2(float x) {
    float y; asm("ex2.approx.f32 %0, %1;" : "=f"(y) : "f"(x));
    return y;
}

#define LDSM_X4(R0,R1,R2,R3,A) \
    asm volatile("ldmatrix.sync.aligned.m8n8.x4.shared.b16 {%0,%1,%2,%3}, [%4];" \
        : "=r"(R0),"=r"(R1),"=r"(R2),"=r"(R3) : "r"(A))
#define MMA16816(D, A0,A1,A2,A3, B0,B1) \
    asm volatile("mma.sync.aligned.m16n8k16.row.col.f32.f16.f16.f32 " \
        "{%0,%1,%2,%3}, {%4,%5,%6,%7}, {%8,%9}, {%0,%1,%2,%3};" \
        : "+f"((D)[0]),"+f"((D)[1]),"+f"((D)[2]),"+f"((D)[3]) \
        : "r"(A0),"r"(A1),"r"(A2),"r"(A3),"r"(B0),"r"(B1))

static __device__ __forceinline__ void cpa16(uint32_t dst, const void* src) {
    asm volatile("cp.async.cg.shared.global [%0], [%1], 16;" :: "r"(dst), "l"(src));
}
#define CP_COMMIT() asm volatile("cp.async.commit_group;" ::: "memory")
#define CP_WAIT(n)  asm volatile("cp.async.wait_group %0;" :: "n"(n) : "memory")

// ============ prologue: build LDSM-native fragment blobs ============
// K blob (8KB): frag(ks,ng) at offset (ks*4+ng)*512. Row (m,r) 16B holds,
// for e=0..7: K[c = ks*16+(m&1)*8+e][s = ng*16+(m>>1)*8+r]  (the exact
// register content R12's LDSM_X4T produced for mma B-fragments).
// V blob (8KB at +8192): frag(ks,ng) row l holds V[c = ng*16+vrow(l)]
// [s = ks*16+vcol(l) .. +7] - the same 16B rows R12's non-trans LDSM read.
__global__ __launch_bounds__(256) void conv_kv_kernel(
    const float* __restrict__ qkv, const float* __restrict__ ekv)
{
    const int st = blockIdx.x;   // 0..39
    const int bh = blockIdx.y;   // 0..31
    const int b = bh >> 4, h = bh & 15;
    const float* qbase  = qkv + ((size_t)b * 3072 + (size_t)h * 192) * 2048;
    const float* kbase  = qbase + (size_t)64  * 2048;
    const float* vbase  = qbase + (size_t)128 * 2048;
    const float* ekbase = ekv + ((size_t)b * 2048 + (size_t)h * 128) * 512;
    const float* evbase = ekbase + (size_t)64 * 512;

    const float* ksrc; const float* vsrc; size_t stride;
    if (st < 8) { ksrc = ekbase + st * 64; vsrc = evbase + st * 64; stride = 512; }
    else        { ksrc = kbase + (st - 8) * 64; vsrc = vbase + (st - 8) * 64; stride = 2048; }

    char* dst = g_scratch + ((size_t)bh * NS_TILES + st) * TILE_BYTES;
    const int tid = threadIdx.x;   // 256

    // ---- K blob: 512 rows of 16B, 2 per thread ----
    #pragma unroll
    for (int it = 0; it < 2; ++it) {
        int R = tid + 256 * it;            // 0..511
        int frag = R >> 5, l = R & 31;
        int ks = frag >> 2, ng = frag & 3;
        int m = l >> 3, r = l & 7;
        int s  = ng * 16 + ((m >> 1) << 3) + r;
        int c0 = ks * 16 + ((m & 1) << 3);
        const float* base = ksrc + (size_t)c0 * stride + s;
        uint32_t w[4];
        #pragma unroll
        for (int e2 = 0; e2 < 4; ++e2) {
            __half2 hh = __floats2half2_rn(base[(size_t)(2 * e2) * stride],
                                           base[(size_t)(2 * e2 + 1) * stride]);
            w[e2] = *(uint32_t*)&hh;
        }
        *(uint4*)(dst + R * 16) = make_uint4(w[0], w[1], w[2], w[3]);
    }

    // ---- V blob: 512 rows of 16B, 2 per thread ----
    #pragma unroll
    for (int it = 0; it < 2; ++it) {
        int R = tid + 256 * it;
        int frag = R >> 5, l = R & 31;
        int ks = frag >> 2, ng = frag & 3;
        int vrow = (l & 7) + ((l >> 4) << 3);
        int vcol = ((l >> 3) & 1) << 3;
        int c  = ng * 16 + vrow;
        int s0 = ks * 16 + vcol;
        const float* p = vsrc + (size_t)c * stride + s0;
        float4 f0 = *(const float4*)(p);
        float4 f1 = *(const float4*)(p + 4);
        __half2 h0 = __floats2half2_rn(f0.x, f0.y);
        __half2 h1 = __floats2half2_rn(f0.z, f0.w);
        __half2 h2 = __floats2half2_rn(f1.x, f1.y);
        __half2 h3 = __floats2half2_rn(f1.z, f1.w);
        *(uint4*)(dst + 8192 + R * 16) =
            make_uint4(*(uint32_t*)&h0, *(uint32_t*)&h1,
                       *(uint32_t*)&h2, *(uint32_t*)&h3);
    }
}

__global__ __launch_bounds__(NTHREADS, 4) void qkv_attn_mma(
    const float* __restrict__ qkv,
    float* __restrict__ out)
{
    extern __shared__ char smb[];
    const uint32_t sb = smem_u32(smb);
    const int tid  = threadIdx.x;
    const int wid  = tid >> 5;          // 0..3
    const int lane = tid & 31;
    const int m0   = wid * 16;          // this warp's query rows [m0, m0+16)
    const uint32_t lane16 = (uint32_t)lane << 4;

    const int t_tile = blockIdx.x;      // 0..31 (64-query tiles)
    const int bh     = blockIdx.y;      // 0..31
    const int b = bh >> 4;
    const int h = bh & 15;
    const int t0 = t_tile * 64;

    const float* qbase = qkv + ((size_t)b * 3072 + (size_t)h * 192) * 2048;
    const char*  kv0   = g_scratch + (size_t)bh * NS_TILES * TILE_BYTES;

    // ---- start tile 0 load (16KB / 128 thr = 8 x 16B each) ----
    {
        const char* src = kv0 + tid * 16;
        uint32_t d = sb + SM_BUF0 + tid * 16;
        #pragma unroll
        for (int i = 0; i < 8; ++i) cpa16(d + i * 2048, src + i * 2048);
        CP_COMMIT();
    }

    // ---- stage Q [64t x 64c] fp16 (transpose + scale*log2e) ----
    #pragma unroll 1
    for (int ci = 0; ci < 16; ++ci) {
        int c = wid + 4 * ci;
        const float* qrow = qbase + (size_t)c * 2048 + t0;
        #pragma unroll
        for (int j = 0; j < 2; ++j) {
            int t = lane + 32 * j;
            float x = qrow[t] * (0.125f * 1.44269504f);
            *(__half*)(smb + SM_Q + swz(t, c)) = __float2half_rn(x);
        }
    }
    __syncthreads();

    // ---- Q A-fragments, kept in regs for all 40 tiles ----
    uint32_t qh[4][4];
    {
        int qr  = m0 + (lane & 15);
        int qcg = (lane >> 4) << 3;
        #pragma unroll
        for (int ks = 0; ks < 4; ++ks)
            LDSM_X4(qh[ks][0], qh[ks][1], qh[ks][2], qh[ks][3],
                    sb + SM_Q + swz(qr, ks * 16 + qcg));
    }

    float o[8][4];
    #pragma unroll
    for (int j = 0; j < 8; ++j)
        #pragma unroll
        for (int r = 0; r < 4; ++r) o[j][r] = 0.0f;
    float l0 = 0.0f, l1 = 0.0f;

    // ring slot bases: cur = st%3, nxt = (st+1)%3
    uint32_t cur_b = sb + SM_BUF0;
    uint32_t nxt_b = sb + SM_BUF0 + TILE_BYTES;

    #pragma unroll 1
    for (int st = 0; st < NS_TILES; ++st) {
        if (st + 1 < NS_TILES) {
            const char* src = kv0 + (size_t)(st + 1) * TILE_BYTES + tid * 16;
            uint32_t d = nxt_b + tid * 16;
            #pragma unroll
            for (int i = 0; i < 8; ++i) cpa16(d + i * 2048, src + i * 2048);
            CP_COMMIT();
            CP_WAIT(1);
        } else {
            CP_WAIT(0);
        }
        __syncthreads();   // only barrier per tile (triple buffer)

        const uint32_t kf = cur_b + lane16;          // K blob, this lane
        const uint32_t vf = kf + 8192;               // V blob, this lane
        cur_b = nxt_b;
        nxt_b = nxt_b + TILE_BYTES;
        if (nxt_b == sb + SM_BUF0 + 3 * TILE_BYTES) nxt_b = sb + SM_BUF0;

        // ---- GEMM1: D[16t x 64s] = Q x K; addresses are base+imm ----
        float d[8][4];
        #pragma unroll
        for (int j = 0; j < 8; ++j)
            #pragma unroll
            for (int r = 0; r < 4; ++r) d[j][r] = 0.0f;

        #pragma unroll
        for (int ks = 0; ks < 4; ++ks) {
            #pragma unroll
            for (int ng = 0; ng < 4; ++ng) {
                uint32_t b0, b1, b2, b3;
                LDSM_X4(b0, b1, b2, b3, kf + (ks * 4 + ng) * 512);
                MMA16816(d[2 * ng],     qh[ks][0], qh[ks][1], qh[ks][2], qh[ks][3], b0, b1);
                MMA16816(d[2 * ng + 1], qh[ks][0], qh[ks][1], qh[ks][2], qh[ks][3], b2, b3);
            }
        }

        // ---- softmax p = 2^score (log2e folded into Q); pack P fragments ----
        uint32_t pa[4][4];
        #pragma unroll
        for (int j = 0; j < 8; ++j) {
            float p0 = ex2(d[j][0]);
            float p1 = ex2(d[j][1]);
            float p2 = ex2(d[j][2]);
            float p3 = ex2(d[j][3]);
            l0 += p0 + p1;
            l1 += p2 + p3;
            __half2 h01 = __floats2half2_rn(p0, p1);
            __half2 h23 = __floats2half2_rn(p2, p3);
            int ks = j >> 1, q = (j & 1) * 2;
            pa[ks][q]     = *(uint32_t*)&h01;
            pa[ks][q + 1] = *(uint32_t*)&h23;
        }

        // ---- GEMM2: O[16t x 64c] += P x V; addresses are base+imm ----
        #pragma unroll
        for (int ks = 0; ks < 4; ++ks) {
            #pragma unroll
            for (int ng = 0; ng < 4; ++ng) {
                uint32_t b0, b1, b2, b3;
                LDSM_X4(b0, b1, b2, b3, vf + (ks * 4 + ng) * 512);
                MMA16816(o[2 * ng],     pa[ks][0], pa[ks][1], pa[ks][2], pa[ks][3], b0, b1);
                MMA16816(o[2 * ng + 1], pa[ks][0], pa[ks][1], pa[ks][2], pa[ks][3], b2, b3);
            }
        }
        // no trailing barrier: triple buffer guarantees no write/read overlap
    }

    // ---- epilogue: row sums across the 4 lanes sharing a row, then STG ----
    l0 += __shfl_xor_sync(0xffffffffu, l0, 1);
    l0 += __shfl_xor_sync(0xffffffffu, l0, 2);
    l1 += __shfl_xor_sync(0xffffffffu, l1, 1);
    l1 += __shfl_xor_sync(0xffffffffu, l1, 2);
    float rl0 = 1.0f / l0;
    float rl1 = 1.0f / l1;

    const int tg = t0 + m0 + (lane >> 2);      // global t of this row
    #pragma unroll
    for (int j = 0; j < 8; ++j) {
        int c = j * 8 + (lane & 3) * 2;
        float* p = out + ((size_t)(b * 1024 + h * 64 + c)) * 2048 + tg;
        p[0]        = o[j][0] * rl0;
        p[2048]     = o[j][1] * rl0;
        p[8]        = o[j][2] * rl1;
        p[2048 + 8] = o[j][3] * rl1;
    }
}

extern "C" void kernel_launch(void* const* d_in, const int* in_sizes, int n_in,
                              void* d_out, int out_size)
{
    const float* qkv;
    const float* ekv;
    if (in_sizes[0] == 2 * 3072 * 2048) {
        qkv = (const float*)d_in[0];
        ekv = (const float*)d_in[1];
    } else {
        qkv = (const float*)d_in[1];
        ekv = (const float*)d_in[0];
    }
    float* out = (float*)d_out;

    // prologue: pre-convert K/V into LDSM-native fragment blobs
    dim3 cgrid(NS_TILES, 32);
    conv_kv_kernel<<<cgrid, 256>>>(qkv, ekv);

    cudaFuncSetAttribute(qkv_attn_mma,
                         cudaFuncAttributeMaxDynamicSharedMemorySize, SM_TOTAL);
    dim3 grid(32, 32);   // (t-tiles of 64, batch-heads)
    qkv_attn_mma<<<grid, NTHREADS, SM_TOTAL>>>(qkv, out);
}